// round 14
// baseline (speedup 1.0000x reference)
#include <cuda_runtime.h>
#include <cuda_bf16.h>

namespace {
constexpr int B = 512, S = 96, N = 64, H = 512, E = 512;
constexpr int NE = E + N;
constexpr int NTHREADS = 256;
constexpr int KC = 192;                   // conv im2col K

// ---- kernel1 shared memory layout ----
constexpr int W_SRC  = 0;                 // int[576]
constexpr int W_DST  = W_SRC + NE;        // int[576]
constexpr int W_DEG  = W_DST + NE;        // int[64]
constexpr int W_OFFS = W_DEG + N;         // int[65]
constexpr int W_CNT  = W_OFFS + N + 1;    // int[64]
constexpr int W_EID  = W_CNT + N;         // int[576]
constexpr int W_DINV = W_EID + NE;        // float[64]
constexpr int META_RAW = W_DINV + N;      // 1985
constexpr int META_END = (META_RAW + 3) & ~3;     // 1988

constexpr int XT_LD  = 98;
constexpr int W_XT   = META_END;                  // float[64][98] (x^T, later t2)
constexpr int U0_BYTES = (W_XT + N * XT_LD) * 4;  // 33040, 16B aligned

// bf16 regions (byte offsets)
constexpr int AG_LD   = 104;                      // xagg bf16 row stride (elems)
constexpr int XAGG_HI_B = U0_BYTES;               // [64][104] bf16
constexpr int XAGG_LO_B = XAGG_HI_B + N * AG_LD * 2;   // 46352
constexpr int H1_LD   = 136;                      // h1 tile bf16 row stride (elems)
constexpr int H1_HI_B = XAGG_LO_B + N * AG_LD * 2;     // 59664
constexpr int H1_LO_B = H1_HI_B + N * H1_LD * 2;       // 77072
constexpr int SMEM1_BYTES = H1_LO_B + N * H1_LD * 2;   // 94480 -> 2 CTAs/SM

static_assert((XAGG_HI_B % 16) == 0 && (XAGG_LO_B % 16) == 0, "ag align");
static_assert((H1_HI_B % 16) == 0 && (H1_LO_B % 16) == 0, "h1 align");

// ---- kernel2 ----
constexpr int BK_LD = 200;                        // bf16 elems per im2col row
constexpr int SMEM2_BYTES = 2 * 96 * BK_LD * 2;   // 76.8 KB -> 2 CTAs/SM
}

// ---- device scratch (static; no allocations) ----
__device__ float         g_h2[(size_t)B * N * S];       // 12.6 MB
__device__ __nv_bfloat16 g_whi[(size_t)H * KC];
__device__ __nv_bfloat16 g_wlo[(size_t)H * KC];
__device__ __nv_bfloat16 g_w1hi[(size_t)H * S];         // W1 [512][96]
__device__ __nv_bfloat16 g_w1lo[(size_t)H * S];
__device__ __nv_bfloat16 g_w2hi[(size_t)S * H];         // W2 [96][512]
__device__ __nv_bfloat16 g_w2lo[(size_t)S * H];

// ---- helpers ----
__device__ __forceinline__ unsigned smem_u32_of(const void* p) {
    unsigned a;
    asm("{ .reg .u64 t; cvta.to.shared.u64 t, %1; cvt.u32.u64 %0, t; }"
        : "=r"(a) : "l"(p));
    return a;
}
__device__ __forceinline__ void ldsm_x4(unsigned* r, unsigned saddr) {
    asm volatile("ldmatrix.sync.aligned.m8n8.x4.shared.b16 {%0,%1,%2,%3}, [%4];"
                 : "=r"(r[0]), "=r"(r[1]), "=r"(r[2]), "=r"(r[3]) : "r"(saddr));
}
__device__ __forceinline__ void mma16816(float* c, const unsigned* a,
                                         unsigned b0, unsigned b1) {
    asm volatile(
        "mma.sync.aligned.m16n8k16.row.col.f32.bf16.bf16.f32 "
        "{%0,%1,%2,%3}, {%4,%5,%6,%7}, {%8,%9}, {%0,%1,%2,%3};"
        : "+f"(c[0]), "+f"(c[1]), "+f"(c[2]), "+f"(c[3])
        : "r"(a[0]), "r"(a[1]), "r"(a[2]), "r"(a[3]), "r"(b0), "r"(b1));
}
__device__ __forceinline__ unsigned pack_bf2(__nv_bfloat16 lo, __nv_bfloat16 hi) {
    __nv_bfloat162 p(lo, hi);
    return *reinterpret_cast<unsigned*>(&p);
}

// ================= kernel0: split conv_w, W1, W2 to bf16 hi/lo =================
__global__ void weights_split_kernel(const float* __restrict__ cw,
                                     const float* __restrict__ W1,
                                     const float* __restrict__ W2) {
    int i = blockIdx.x * blockDim.x + threadIdx.x;
    if (i < H * KC) {
        float v = cw[i];
        __nv_bfloat16 hv = __float2bfloat16(v);
        g_whi[i] = hv;
        g_wlo[i] = __float2bfloat16(v - __bfloat162float(hv));
    }
    int j = i - H * KC;
    if (j >= 0 && j < H * S) {
        float v = W1[j];
        __nv_bfloat16 hv = __float2bfloat16(v);
        g_w1hi[j] = hv;
        g_w1lo[j] = __float2bfloat16(v - __bfloat162float(hv));
        float v2 = W2[j];
        __nv_bfloat16 hv2 = __float2bfloat16(v2);
        g_w2hi[j] = hv2;
        g_w2lo[j] = __float2bfloat16(v2 - __bfloat162float(hv2));
    }
}

// ================= kernel1: GCN phases 0-4, GEMMs on tensor pipe =================
__global__ __launch_bounds__(NTHREADS, 2)
void gcn_front_kernel(const float* __restrict__ x,
                      const int*   __restrict__ edge_index,
                      const float* __restrict__ b1,
                      const float* __restrict__ b2)
{
    extern __shared__ float sm[];
    int*   s_src  = (int*)(sm + W_SRC);
    int*   s_dst  = (int*)(sm + W_DST);
    int*   s_deg  = (int*)(sm + W_DEG);
    int*   s_off  = (int*)(sm + W_OFFS);
    int*   s_cnt  = (int*)(sm + W_CNT);
    int*   s_eid  = (int*)(sm + W_EID);
    float* s_dinv = sm + W_DINV;
    float* s_xT   = sm + W_XT;    // [64][98]; x^T, later t2
    char*  smc    = (char*)sm;

    const int tid = threadIdx.x;
    const int bid = blockIdx.x;

    // ---------- Phase 0: edges, x^T, degrees, CSR ----------
    const int* ei = edge_index + (size_t)bid * 2 * E;
    for (int i = tid; i < E; i += NTHREADS) {
        s_src[i] = ei[i];
        s_dst[i] = ei[E + i];
    }
    if (tid < N) {
        s_src[E + tid] = tid;
        s_dst[E + tid] = tid;
        s_deg[tid] = 0;
        s_cnt[tid] = 0;
    }
    const float* xb = x + (size_t)bid * S * N;
    for (int i = tid; i < S * N; i += NTHREADS) {
        int s = i >> 6, n = i & 63;
        s_xT[n * XT_LD + s] = xb[i];
    }
    __syncthreads();

    for (int i = tid; i < NE; i += NTHREADS) atomicAdd(&s_deg[s_dst[i]], 1);
    __syncthreads();
    if (tid < N) s_dinv[tid] = rsqrtf((float)s_deg[tid]);
    if (tid == 0) {
        int acc = 0;
        for (int n = 0; n < N; n++) { s_off[n] = acc; acc += s_deg[n]; }
        s_off[N] = acc;
    }
    __syncthreads();
    for (int i = tid; i < NE; i += NTHREADS) {
        int d = s_dst[i];
        int pos = s_off[d] + atomicAdd(&s_cnt[d], 1);
        s_eid[pos] = i;
    }
    __syncthreads();

    // ---------- Phase 1: xagg = A_hat * x^T -> bf16 hi/lo ----------
    for (int p = tid; p < N * S; p += NTHREADS) {
        int n = p & 63, s = p >> 6;
        float acc = 0.f;
        const int e0 = s_off[n], e1 = s_off[n + 1];
        for (int q = e0; q < e1; q++) {
            int sr = s_src[s_eid[q]];
            acc += s_dinv[sr] * s_xT[sr * XT_LD + s];
        }
        float v = acc * s_dinv[n];
        __nv_bfloat16 hv = __float2bfloat16(v);
        __nv_bfloat16 lv = __float2bfloat16(v - __bfloat162float(hv));
        *(__nv_bfloat16*)(smc + XAGG_HI_B + (n * AG_LD + s) * 2) = hv;
        *(__nv_bfloat16*)(smc + XAGG_LO_B + (n * AG_LD + s) * 2) = lv;
    }
    __syncthreads();

    // ---------- Phases 2+3: mma GEMM1 (relu) + GEMM2, H-tiled ----------
    const int lane = tid & 31;
    const int wid  = tid >> 5;
    const int gid  = lane >> 2;
    const int tig  = lane & 3;
    const int wr   = wid & 3;       // warp row (m)
    const int wc   = wid >> 2;      // warp col (n)
    const int m0   = 16 * wr;

    const unsigned sbase   = smem_u32_of(sm);
    const unsigned ag_hi_s = sbase + XAGG_HI_B;
    const unsigned ag_lo_s = sbase + XAGG_LO_B;
    const unsigned h1_hi_s = sbase + H1_HI_B;
    const unsigned h1_lo_s = sbase + H1_LO_B;
    const unsigned arow16  = (unsigned)(m0 + (lane & 15));
    const unsigned asel16  = (unsigned)((lane >> 4) * 16);

    float t2acc[6][4];
    #pragma unroll
    for (int nt = 0; nt < 6; nt++)
        #pragma unroll
        for (int q = 0; q < 4; q++) t2acc[nt][q] = 0.f;

    for (int ht = 0; ht < 4; ht++) {
        // --- GEMM1 tile in two half-passes of 4 n-tiles (16 acc regs) ---
        #pragma unroll 1
        for (int half = 0; half < 2; half++) {
            float acc1[4][4];
            #pragma unroll
            for (int nt = 0; nt < 4; nt++)
                #pragma unroll
                for (int q = 0; q < 4; q++) acc1[nt][q] = 0.f;

            for (int kk = 0; kk < 6; kk++) {
                unsigned ah[4], al[4];
                unsigned aoff = arow16 * (AG_LD * 2) + kk * 32 + asel16;
                ldsm_x4(ah, ag_hi_s + aoff);
                ldsm_x4(al, ag_lo_s + aoff);
                #pragma unroll
                for (int nt = 0; nt < 4; nt++) {
                    int n = ht * 128 + wc * 64 + half * 32 + nt * 8 + gid;
                    int bo = n * S + kk * 16 + 2 * tig;
                    unsigned bh0 = *(const unsigned*)&g_w1hi[bo];
                    unsigned bh1 = *(const unsigned*)&g_w1hi[bo + 8];
                    unsigned bl0 = *(const unsigned*)&g_w1lo[bo];
                    unsigned bl1 = *(const unsigned*)&g_w1lo[bo + 8];
                    mma16816(acc1[nt], ah, bh0, bh1);
                    mma16816(acc1[nt], ah, bl0, bl1);
                    mma16816(acc1[nt], al, bh0, bh1);
                }
            }
            // bias + relu + bf16 split -> h1 tile smem
            #pragma unroll
            for (int nt = 0; nt < 4; nt++) {
                int hc = ht * 128 + wc * 64 + half * 32 + nt * 8 + 2 * tig;
                int lc = wc * 64 + half * 32 + nt * 8 + 2 * tig;
                float bv0 = b1[hc], bv1 = b1[hc + 1];
                float v0 = fmaxf(acc1[nt][0] + bv0, 0.f);
                float v1 = fmaxf(acc1[nt][1] + bv1, 0.f);
                float v2 = fmaxf(acc1[nt][2] + bv0, 0.f);
                float v3 = fmaxf(acc1[nt][3] + bv1, 0.f);
                __nv_bfloat16 h0 = __float2bfloat16(v0), h1v = __float2bfloat16(v1);
                __nv_bfloat16 h2v = __float2bfloat16(v2), h3 = __float2bfloat16(v3);
                __nv_bfloat16 l0 = __float2bfloat16(v0 - __bfloat162float(h0));
                __nv_bfloat16 l1 = __float2bfloat16(v1 - __bfloat162float(h1v));
                __nv_bfloat16 l2 = __float2bfloat16(v2 - __bfloat162float(h2v));
                __nv_bfloat16 l3 = __float2bfloat16(v3 - __bfloat162float(h3));
                unsigned ra = (m0 + gid) * (H1_LD * 2) + lc * 2;
                unsigned rb = (m0 + gid + 8) * (H1_LD * 2) + lc * 2;
                *(unsigned*)(smc + H1_HI_B + ra) = pack_bf2(h0, h1v);
                *(unsigned*)(smc + H1_LO_B + ra) = pack_bf2(l0, l1);
                *(unsigned*)(smc + H1_HI_B + rb) = pack_bf2(h2v, h3);
                *(unsigned*)(smc + H1_LO_B + rb) = pack_bf2(l2, l3);
            }
        }
        __syncthreads();

        // --- GEMM2 accumulate: t2[m=64, s=96] += h1_tile @ W2_tile^T ---
        for (int kk = 0; kk < 8; kk++) {
            unsigned ah[4], al[4];
            unsigned aoff = arow16 * (H1_LD * 2) + kk * 32 + asel16;
            ldsm_x4(ah, h1_hi_s + aoff);
            ldsm_x4(al, h1_lo_s + aoff);
            #pragma unroll
            for (int nt = 0; nt < 6; nt++) {
                int n = wc * 48 + nt * 8 + gid;          // s index
                int bo = n * H + ht * 128 + kk * 16 + 2 * tig;
                unsigned bh0 = *(const unsigned*)&g_w2hi[bo];
                unsigned bh1 = *(const unsigned*)&g_w2hi[bo + 8];
                unsigned bl0 = *(const unsigned*)&g_w2lo[bo];
                unsigned bl1 = *(const unsigned*)&g_w2lo[bo + 8];
                mma16816(t2acc[nt], ah, bh0, bh1);
                mma16816(t2acc[nt], ah, bl0, bl1);
                mma16816(t2acc[nt], al, bh0, bh1);
            }
        }
        __syncthreads();   // h1 tile reusable next iteration
    }

    // write t2 -> s_xT fp32 [node][s]
    #pragma unroll
    for (int nt = 0; nt < 6; nt++) {
        int n0 = wc * 48 + nt * 8 + 2 * tig;
        s_xT[(m0 + gid) * XT_LD + n0]         = t2acc[nt][0];
        s_xT[(m0 + gid) * XT_LD + n0 + 1]     = t2acc[nt][1];
        s_xT[(m0 + gid + 8) * XT_LD + n0]     = t2acc[nt][2];
        s_xT[(m0 + gid + 8) * XT_LD + n0 + 1] = t2acc[nt][3];
    }
    __syncthreads();

    // ---------- Phase 4: aggregate t2 (+b2) -> g_h2[b][n][s] ----------
    float* h2b = g_h2 + (size_t)bid * N * S;
    for (int p = tid; p < N * S; p += NTHREADS) {
        int n = p & 63, s = p >> 6;
        float acc = 0.f;
        const int e0 = s_off[n], e1 = s_off[n + 1];
        for (int q = e0; q < e1; q++) {
            int sr = s_src[s_eid[q]];
            acc += s_dinv[sr] * s_xT[sr * XT_LD + s];
        }
        h2b[n * S + s] = acc * s_dinv[n] + b2[s];
    }
}

// ================= kernel2: conv as 3-pass bf16 mma.sync GEMM =================
__global__ __launch_bounds__(NTHREADS, 2)
void conv_mma_kernel(float* __restrict__ out)
{
    extern __shared__ __nv_bfloat16 smb[];
    __nv_bfloat16* Bhi = smb;                 // [96][BK_LD]
    __nv_bfloat16* Blo = smb + 96 * BK_LD;    // [96][BK_LD]

    const int tid = threadIdx.x;
    const int bid = blockIdx.x;
    const int lane = tid & 31;
    const int wid  = tid >> 5;
    const int gid  = lane >> 2;
    const int tig  = lane & 3;

    // ---- build im2col B (hi/lo): B[s][K] = h2[ic][(s+k-1) mod 96], K = ic*3+k ----
    const float* h2b = g_h2 + (size_t)bid * N * S;
    for (int i = tid; i < 96 * KC; i += NTHREADS) {
        int s = i / KC, K = i - s * KC;
        int ic = K / 3, k = K - ic * 3;
        int t = s + k - 1;
        if (t < 0) t += 96;
        if (t >= 96) t -= 96;
        float v = h2b[ic * S + t];
        __nv_bfloat16 hv = __float2bfloat16(v);
        Bhi[s * BK_LD + K] = hv;
        Blo[s * BK_LD + K] = __float2bfloat16(v - __bfloat162float(hv));
    }
    __syncthreads();

    float* outb = out + (size_t)bid * S * H;
    const int o0 = wid * 64;

    for (int mt = 0; mt < 4; mt++) {
        const int m = o0 + mt * 16;
        float acc[12][4];
        #pragma unroll
        for (int nt = 0; nt < 12; nt++)
            #pragma unroll
            for (int q = 0; q < 4; q++) acc[nt][q] = 0.f;

        const int r0 = (m + gid) * KC;
        const int r1 = (m + gid + 8) * KC;

        for (int kc = 0; kc < 12; kc++) {
            const int c0 = kc * 16 + 2 * tig;
            unsigned ahi[4], alo[4];
            ahi[0] = *(const unsigned*)&g_whi[r0 + c0];
            ahi[1] = *(const unsigned*)&g_whi[r1 + c0];
            ahi[2] = *(const unsigned*)&g_whi[r0 + c0 + 8];
            ahi[3] = *(const unsigned*)&g_whi[r1 + c0 + 8];
            alo[0] = *(const unsigned*)&g_wlo[r0 + c0];
            alo[1] = *(const unsigned*)&g_wlo[r1 + c0];
            alo[2] = *(const unsigned*)&g_wlo[r0 + c0 + 8];
            alo[3] = *(const unsigned*)&g_wlo[r1 + c0 + 8];

            #pragma unroll
            for (int nt = 0; nt < 12; nt++) {
                const int row = nt * 8 + gid;
                unsigned bh0 = *(const unsigned*)&Bhi[row * BK_LD + c0];
                unsigned bh1 = *(const unsigned*)&Bhi[row * BK_LD + c0 + 8];
                unsigned bl0 = *(const unsigned*)&Blo[row * BK_LD + c0];
                unsigned bl1 = *(const unsigned*)&Blo[row * BK_LD + c0 + 8];
                mma16816(acc[nt], ahi, bh0, bh1);
                mma16816(acc[nt], ahi, bl0, bl1);
                mma16816(acc[nt], alo, bh0, bh1);
            }
        }

        // ---- write D[o][s] -> out[b][s][o] ----
        #pragma unroll
        for (int nt = 0; nt < 12; nt++) {
            const int s0 = nt * 8 + 2 * tig;
            const int o  = m + gid;
            outb[(size_t)s0 * H + o]           = acc[nt][0];
            outb[(size_t)(s0 + 1) * H + o]     = acc[nt][1];
            outb[(size_t)s0 * H + o + 8]       = acc[nt][2];
            outb[(size_t)(s0 + 1) * H + o + 8] = acc[nt][3];
        }
    }
}

extern "C" void kernel_launch(void* const* d_in, const int* in_sizes, int n_in,
                              void* d_out, int out_size)
{
    const float* x   = (const float*)d_in[0];
    const int*   ei  = (const int*)  d_in[1];
    const float* W1  = (const float*)d_in[2];
    const float* b1  = (const float*)d_in[3];
    const float* W2  = (const float*)d_in[4];
    const float* b2  = (const float*)d_in[5];
    const float* cw  = (const float*)d_in[6];
    float* out = (float*)d_out;

    weights_split_kernel<<<(H * KC + H * S + 255) / 256, 256>>>(cw, W1, W2);

    cudaFuncSetAttribute(gcn_front_kernel,
                         cudaFuncAttributeMaxDynamicSharedMemorySize, SMEM1_BYTES);
    gcn_front_kernel<<<B, NTHREADS, SMEM1_BYTES>>>(x, ei, b1, b2);

    cudaFuncSetAttribute(conv_mma_kernel,
                         cudaFuncAttributeMaxDynamicSharedMemorySize, SMEM2_BYTES);
    conv_mma_kernel<<<B, NTHREADS, SMEM2_BYTES>>>(out);
}

// round 15
// speedup vs baseline: 1.6952x; 1.6952x over previous
#include <cuda_runtime.h>
#include <cuda_bf16.h>

namespace {
constexpr int B = 512, S = 96, N = 64, H = 512, E = 512;
constexpr int NE = E + N;
constexpr int NTHREADS = 256;
constexpr int KC = 192;                   // conv im2col K

// ---- fused kernel shared memory layout ----
constexpr int W_SRC  = 0;                 // int[576]
constexpr int W_DST  = W_SRC + NE;        // int[576]
constexpr int W_DEG  = W_DST + NE;        // int[64]
constexpr int W_OFFS = W_DEG + N;         // int[65]
constexpr int W_CNT  = W_OFFS + N + 1;    // int[64]
constexpr int W_EID  = W_CNT + N;         // int[576]
constexpr int W_DINV = W_EID + NE;        // float[64]
constexpr int META_RAW = W_DINV + N;      // 1985
constexpr int META_END = (META_RAW + 3) & ~3;     // 1988

constexpr int XT_LD  = 98;
constexpr int W_XT   = META_END;                  // float[64][98] (x^T, later t2)
constexpr int U0_BYTES = (W_XT + N * XT_LD) * 4;  // 33040, 16B aligned

// --- GEMM-phase view of union region (byte offsets) ---
constexpr int AG_LD   = 104;                      // xagg bf16 row stride (elems)
constexpr int XAGG_HI_B = U0_BYTES;               // [64][104] bf16
constexpr int XAGG_LO_B = XAGG_HI_B + N * AG_LD * 2;   // 46352
constexpr int H1_LD   = 136;                      // h1 tile bf16 row stride (elems)
constexpr int H1_HI_B = XAGG_LO_B + N * AG_LD * 2;     // 59664
constexpr int H1_LO_B = H1_HI_B + N * H1_LD * 2;       // 77072  (end 94480)

// --- conv-phase view of union region ---
constexpr int BK_LD = 200;                        // bf16 elems per im2col row
constexpr int CONV_BHI_B = U0_BYTES;              // [96][200] bf16 = 38400 B
constexpr int CONV_BLO_B = CONV_BHI_B + 96 * BK_LD * 2;   // 71440
constexpr int CONV_END_B = CONV_BLO_B + 96 * BK_LD * 2;   // 109840

constexpr int SMEM_BYTES = CONV_END_B;            // 109.8 KB -> 2 CTAs/SM

static_assert((XAGG_HI_B % 16) == 0 && (XAGG_LO_B % 16) == 0, "ag align");
static_assert((H1_HI_B % 16) == 0 && (H1_LO_B % 16) == 0, "h1 align");
static_assert((CONV_BHI_B % 16) == 0 && (CONV_BLO_B % 16) == 0, "conv align");

// fragment array sizes (unsigned words)
constexpr int F1_WORDS = 64 * 6 * 32 * 2;         // 24576 (n-tiles x kk x lane x b)
constexpr int F2_WORDS = 12 * 32 * 32 * 2;        // 24576 (s-tiles x kgrp x lane x b)
constexpr int FC_WORDS = 32 * 12 * 32 * 4;        // 49152 (m-tiles x kc x lane x q)
}

// ---- device scratch (static; no allocations) ----
__device__ unsigned g_f1hi[F1_WORDS], g_f1lo[F1_WORDS];
__device__ unsigned g_f2hi[F2_WORDS], g_f2lo[F2_WORDS];
__device__ unsigned g_fchi[FC_WORDS], g_fclo[FC_WORDS];

// ---- helpers ----
__device__ __forceinline__ unsigned smem_u32_of(const void* p) {
    unsigned a;
    asm("{ .reg .u64 t; cvta.to.shared.u64 t, %1; cvt.u32.u64 %0, t; }"
        : "=r"(a) : "l"(p));
    return a;
}
__device__ __forceinline__ void ldsm_x4(unsigned* r, unsigned saddr) {
    asm volatile("ldmatrix.sync.aligned.m8n8.x4.shared.b16 {%0,%1,%2,%3}, [%4];"
                 : "=r"(r[0]), "=r"(r[1]), "=r"(r[2]), "=r"(r[3]) : "r"(saddr));
}
__device__ __forceinline__ void mma16816(float* c, const unsigned* a,
                                         unsigned b0, unsigned b1) {
    asm volatile(
        "mma.sync.aligned.m16n8k16.row.col.f32.bf16.bf16.f32 "
        "{%0,%1,%2,%3}, {%4,%5,%6,%7}, {%8,%9}, {%0,%1,%2,%3};"
        : "+f"(c[0]), "+f"(c[1]), "+f"(c[2]), "+f"(c[3])
        : "r"(a[0]), "r"(a[1]), "r"(a[2]), "r"(a[3]), "r"(b0), "r"(b1));
}
__device__ __forceinline__ unsigned pack_bf2(__nv_bfloat16 lo, __nv_bfloat16 hi) {
    __nv_bfloat162 p(lo, hi);
    return *reinterpret_cast<unsigned*>(&p);
}
__device__ __forceinline__ void split_pair(float v0, float v1,
                                           unsigned& whi, unsigned& wlo) {
    __nv_bfloat16 h0 = __float2bfloat16(v0), h1 = __float2bfloat16(v1);
    __nv_bfloat16 l0 = __float2bfloat16(v0 - __bfloat162float(h0));
    __nv_bfloat16 l1 = __float2bfloat16(v1 - __bfloat162float(h1));
    whi = pack_bf2(h0, h1);
    wlo = pack_bf2(l0, l1);
}

// ================= kernel0: prepack weights into mma-fragment order =================
__global__ void weights_prepack_kernel(const float* __restrict__ W1,
                                       const float* __restrict__ W2,
                                       const float* __restrict__ cw) {
    int idx = blockIdx.x * blockDim.x + threadIdx.x;
    if (idx < F1_WORDS) {
        // W1 B-fragments: T (8-col n-tile), kk (k-chunk of 16), lane, b
        int T = idx / 384, r = idx % 384;
        int kk = r / 64, r2 = r % 64;
        int lane = r2 >> 1, b = r2 & 1;
        int n = T * 8 + (lane >> 2);
        int k = kk * 16 + 2 * (lane & 3) + b * 8;
        split_pair(W1[(size_t)n * S + k], W1[(size_t)n * S + k + 1],
                   g_f1hi[idx], g_f1lo[idx]);
        return;
    }
    int i2 = idx - F1_WORDS;
    if (i2 < F2_WORDS) {
        // W2 B-fragments: T2 (8-row s-tile), kgrp (k-chunk of 16 within H), lane, b
        int T2 = i2 / 2048, r = i2 % 2048;
        int kg = r / 64, r2 = r % 64;
        int lane = r2 >> 1, b = r2 & 1;
        int s = T2 * 8 + (lane >> 2);
        int k = kg * 16 + 2 * (lane & 3) + b * 8;
        split_pair(W2[(size_t)s * H + k], W2[(size_t)s * H + k + 1],
                   g_f2hi[i2], g_f2lo[i2]);
        return;
    }
    int i3 = i2 - F2_WORDS;
    if (i3 < FC_WORDS) {
        // conv A-fragments: mt (16-row m-tile), kc (k-chunk of 16), lane, q
        int mt = i3 / 1536, r = i3 % 1536;
        int kc = r / 128, r2 = r % 128;
        int lane = r2 >> 2, q = r2 & 3;
        int row = mt * 16 + (lane >> 2) + (q & 1) * 8;
        int col = kc * 16 + 2 * (lane & 3) + (q >> 1) * 8;
        split_pair(cw[(size_t)row * KC + col], cw[(size_t)row * KC + col + 1],
                   g_fchi[i3], g_fclo[i3]);
    }
}

// ================= fused kernel: GCN + conv, all GEMMs on tensor pipe =================
__global__ __launch_bounds__(NTHREADS, 2)
void gcn_fused_kernel(const float* __restrict__ x,
                      const int*   __restrict__ edge_index,
                      const float* __restrict__ b1,
                      const float* __restrict__ b2,
                      float*       __restrict__ out)
{
    extern __shared__ float sm[];
    int*   s_src  = (int*)(sm + W_SRC);
    int*   s_dst  = (int*)(sm + W_DST);
    int*   s_deg  = (int*)(sm + W_DEG);
    int*   s_off  = (int*)(sm + W_OFFS);
    int*   s_cnt  = (int*)(sm + W_CNT);
    int*   s_eid  = (int*)(sm + W_EID);
    float* s_dinv = sm + W_DINV;
    float* s_xT   = sm + W_XT;    // [64][98]; x^T, later t2
    char*  smc    = (char*)sm;
    __nv_bfloat16* cBhi = (__nv_bfloat16*)(smc + CONV_BHI_B);
    __nv_bfloat16* cBlo = (__nv_bfloat16*)(smc + CONV_BLO_B);

    const int tid = threadIdx.x;
    const int bid = blockIdx.x;

    // ---------- Phase 0: edges, x^T, degrees, CSR ----------
    const int* ei = edge_index + (size_t)bid * 2 * E;
    for (int i = tid; i < E; i += NTHREADS) {
        s_src[i] = ei[i];
        s_dst[i] = ei[E + i];
    }
    if (tid < N) {
        s_src[E + tid] = tid;
        s_dst[E + tid] = tid;
        s_deg[tid] = 0;
        s_cnt[tid] = 0;
    }
    const float* xb = x + (size_t)bid * S * N;
    for (int i = tid; i < S * N; i += NTHREADS) {
        int s = i >> 6, n = i & 63;
        s_xT[n * XT_LD + s] = xb[i];
    }
    __syncthreads();

    for (int i = tid; i < NE; i += NTHREADS) atomicAdd(&s_deg[s_dst[i]], 1);
    __syncthreads();
    if (tid < N) s_dinv[tid] = rsqrtf((float)s_deg[tid]);
    if (tid == 0) {
        int acc = 0;
        for (int n = 0; n < N; n++) { s_off[n] = acc; acc += s_deg[n]; }
        s_off[N] = acc;
    }
    __syncthreads();
    for (int i = tid; i < NE; i += NTHREADS) {
        int d = s_dst[i];
        int pos = s_off[d] + atomicAdd(&s_cnt[d], 1);
        s_eid[pos] = i;
    }
    __syncthreads();

    // ---------- Phase 1: xagg = A_hat * x^T -> bf16 hi/lo ----------
    for (int p = tid; p < N * S; p += NTHREADS) {
        int n = p & 63, s = p >> 6;
        float acc = 0.f;
        const int e0 = s_off[n], e1 = s_off[n + 1];
        for (int q = e0; q < e1; q++) {
            int sr = s_src[s_eid[q]];
            acc += s_dinv[sr] * s_xT[sr * XT_LD + s];
        }
        float v = acc * s_dinv[n];
        __nv_bfloat16 hv = __float2bfloat16(v);
        __nv_bfloat16 lv = __float2bfloat16(v - __bfloat162float(hv));
        *(__nv_bfloat16*)(smc + XAGG_HI_B + (n * AG_LD + s) * 2) = hv;
        *(__nv_bfloat16*)(smc + XAGG_LO_B + (n * AG_LD + s) * 2) = lv;
    }
    __syncthreads();

    // ---------- Phases 2+3: mma GEMM1 (relu) + GEMM2, H-tiled ----------
    const int lane = tid & 31;
    const int wid  = tid >> 5;
    const int gid  = lane >> 2;
    const int tig  = lane & 3;
    const int wr   = wid & 3;       // warp row (m)
    const int wc   = wid >> 2;      // warp col (n)
    const int m0   = 16 * wr;

    const unsigned sbase   = smem_u32_of(sm);
    const unsigned ag_hi_s = sbase + XAGG_HI_B;
    const unsigned ag_lo_s = sbase + XAGG_LO_B;
    const unsigned h1_hi_s = sbase + H1_HI_B;
    const unsigned h1_lo_s = sbase + H1_LO_B;
    const unsigned arow16  = (unsigned)(m0 + (lane & 15));
    const unsigned asel16  = (unsigned)((lane >> 4) * 16);

    float t2acc[6][4];
    #pragma unroll
    for (int nt = 0; nt < 6; nt++)
        #pragma unroll
        for (int q = 0; q < 4; q++) t2acc[nt][q] = 0.f;

    for (int ht = 0; ht < 4; ht++) {
        // --- GEMM1 tile in two half-passes of 4 n-tiles ---
        #pragma unroll 1
        for (int half = 0; half < 2; half++) {
            float acc1[4][4];
            #pragma unroll
            for (int nt = 0; nt < 4; nt++)
                #pragma unroll
                for (int q = 0; q < 4; q++) acc1[nt][q] = 0.f;

            for (int kk = 0; kk < 6; kk++) {
                unsigned ah[4], al[4];
                unsigned aoff = arow16 * (AG_LD * 2) + kk * 32 + asel16;
                ldsm_x4(ah, ag_hi_s + aoff);
                ldsm_x4(al, ag_lo_s + aoff);
                #pragma unroll
                for (int nt = 0; nt < 4; nt++) {
                    int T = ht * 16 + wc * 8 + half * 4 + nt;    // n-tile
                    int fo = ((T * 6 + kk) * 32 + lane) * 2;
                    uint2 bh = *(const uint2*)&g_f1hi[fo];
                    uint2 bl = *(const uint2*)&g_f1lo[fo];
                    mma16816(acc1[nt], ah, bh.x, bh.y);
                    mma16816(acc1[nt], ah, bl.x, bl.y);
                    mma16816(acc1[nt], al, bh.x, bh.y);
                }
            }
            // bias + relu + bf16 split -> h1 tile smem
            #pragma unroll
            for (int nt = 0; nt < 4; nt++) {
                int hc = ht * 128 + wc * 64 + half * 32 + nt * 8 + 2 * tig;
                int lc = wc * 64 + half * 32 + nt * 8 + 2 * tig;
                float bv0 = b1[hc], bv1 = b1[hc + 1];
                float v0 = fmaxf(acc1[nt][0] + bv0, 0.f);
                float v1 = fmaxf(acc1[nt][1] + bv1, 0.f);
                float v2 = fmaxf(acc1[nt][2] + bv0, 0.f);
                float v3 = fmaxf(acc1[nt][3] + bv1, 0.f);
                unsigned ra = (m0 + gid) * (H1_LD * 2) + lc * 2;
                unsigned rb = (m0 + gid + 8) * (H1_LD * 2) + lc * 2;
                unsigned whi, wlo;
                split_pair(v0, v1, whi, wlo);
                *(unsigned*)(smc + H1_HI_B + ra) = whi;
                *(unsigned*)(smc + H1_LO_B + ra) = wlo;
                split_pair(v2, v3, whi, wlo);
                *(unsigned*)(smc + H1_HI_B + rb) = whi;
                *(unsigned*)(smc + H1_LO_B + rb) = wlo;
            }
        }
        __syncthreads();

        // --- GEMM2 accumulate: t2[m=64, s=96] += h1_tile @ W2_tile^T ---
        for (int kk = 0; kk < 8; kk++) {
            unsigned ah[4], al[4];
            unsigned aoff = arow16 * (H1_LD * 2) + kk * 32 + asel16;
            ldsm_x4(ah, h1_hi_s + aoff);
            ldsm_x4(al, h1_lo_s + aoff);
            int kg = ht * 8 + kk;
            #pragma unroll
            for (int nt = 0; nt < 6; nt++) {
                int T2 = wc * 6 + nt;                    // s-tile
                int fo = ((T2 * 32 + kg) * 32 + lane) * 2;
                uint2 bh = *(const uint2*)&g_f2hi[fo];
                uint2 bl = *(const uint2*)&g_f2lo[fo];
                mma16816(t2acc[nt], ah, bh.x, bh.y);
                mma16816(t2acc[nt], ah, bl.x, bl.y);
                mma16816(t2acc[nt], al, bh.x, bh.y);
            }
        }
        __syncthreads();   // h1 tile reusable next iteration
    }

    // write t2 -> s_xT fp32 [node][s]
    #pragma unroll
    for (int nt = 0; nt < 6; nt++) {
        int n0 = wc * 48 + nt * 8 + 2 * tig;
        s_xT[(m0 + gid) * XT_LD + n0]         = t2acc[nt][0];
        s_xT[(m0 + gid) * XT_LD + n0 + 1]     = t2acc[nt][1];
        s_xT[(m0 + gid + 8) * XT_LD + n0]     = t2acc[nt][2];
        s_xT[(m0 + gid + 8) * XT_LD + n0 + 1] = t2acc[nt][3];
    }
    __syncthreads();

    // ---------- Phase 4: aggregate t2 (+b2) -> conv im2col (hi/lo) directly ----------
    // h2[n][t] lands at B[s][3n+k] for k=0..2, s=(t+1-k) mod 96
    for (int p = tid; p < N * S; p += NTHREADS) {
        int n = p & 63, t = p >> 6;
        float acc = 0.f;
        const int e0 = s_off[n], e1 = s_off[n + 1];
        for (int q = e0; q < e1; q++) {
            int sr = s_src[s_eid[q]];
            acc += s_dinv[sr] * s_xT[sr * XT_LD + t];
        }
        float v = acc * s_dinv[n] + b2[t];
        __nv_bfloat16 hv = __float2bfloat16(v);
        __nv_bfloat16 lv = __float2bfloat16(v - __bfloat162float(hv));
        #pragma unroll
        for (int k = 0; k < 3; k++) {
            int s = t + 1 - k;
            if (s < 0) s += 96;
            if (s >= 96) s -= 96;
            cBhi[s * BK_LD + 3 * n + k] = hv;
            cBlo[s * BK_LD + 3 * n + k] = lv;
        }
    }
    __syncthreads();

    // ---------- Phase 5: conv as 3-pass bf16 mma (prepacked A-fragments) ----------
    float* outb = out + (size_t)bid * S * H;
    const int o0 = wid * 64;

    for (int mt = 0; mt < 4; mt++) {
        const int m = o0 + mt * 16;
        const int mt32 = wid * 4 + mt;              // global 16-row m-tile
        float acc[12][4];
        #pragma unroll
        for (int nt = 0; nt < 12; nt++)
            #pragma unroll
            for (int q = 0; q < 4; q++) acc[nt][q] = 0.f;

        for (int kc = 0; kc < 12; kc++) {
            const int c0 = kc * 16 + 2 * tig;
            int fo = ((mt32 * 12 + kc) * 32 + lane) * 4;
            uint4 a4h = *(const uint4*)&g_fchi[fo];
            uint4 a4l = *(const uint4*)&g_fclo[fo];
            unsigned ahi[4] = {a4h.x, a4h.y, a4h.z, a4h.w};
            unsigned alo[4] = {a4l.x, a4l.y, a4l.z, a4l.w};

            #pragma unroll
            for (int nt = 0; nt < 12; nt++) {
                const int row = nt * 8 + gid;
                unsigned bh0 = *(const unsigned*)&cBhi[row * BK_LD + c0];
                unsigned bh1 = *(const unsigned*)&cBhi[row * BK_LD + c0 + 8];
                unsigned bl0 = *(const unsigned*)&cBlo[row * BK_LD + c0];
                unsigned bl1 = *(const unsigned*)&cBlo[row * BK_LD + c0 + 8];
                mma16816(acc[nt], ahi, bh0, bh1);
                mma16816(acc[nt], ahi, bl0, bl1);
                mma16816(acc[nt], alo, bh0, bh1);
            }
        }

        // ---- write D[o][s] -> out[b][s][o] ----
        #pragma unroll
        for (int nt = 0; nt < 12; nt++) {
            const int s0 = nt * 8 + 2 * tig;
            const int o  = m + gid;
            outb[(size_t)s0 * H + o]           = acc[nt][0];
            outb[(size_t)(s0 + 1) * H + o]     = acc[nt][1];
            outb[(size_t)s0 * H + o + 8]       = acc[nt][2];
            outb[(size_t)(s0 + 1) * H + o + 8] = acc[nt][3];
        }
    }
}

extern "C" void kernel_launch(void* const* d_in, const int* in_sizes, int n_in,
                              void* d_out, int out_size)
{
    const float* x   = (const float*)d_in[0];
    const int*   ei  = (const int*)  d_in[1];
    const float* W1  = (const float*)d_in[2];
    const float* b1  = (const float*)d_in[3];
    const float* W2  = (const float*)d_in[4];
    const float* b2  = (const float*)d_in[5];
    const float* cw  = (const float*)d_in[6];
    float* out = (float*)d_out;

    int total = F1_WORDS + F2_WORDS + FC_WORDS;
    weights_prepack_kernel<<<(total + 255) / 256, 256>>>(W1, W2, cw);

    cudaFuncSetAttribute(gcn_fused_kernel,
                         cudaFuncAttributeMaxDynamicSharedMemorySize, SMEM_BYTES);
    gcn_fused_kernel<<<B, NTHREADS, SMEM_BYTES>>>(x, ei, b1, b2, out);
}